// round 1
// baseline (speedup 1.0000x reference)
#include <cuda_runtime.h>
#include <math.h>

// Problem constants (fixed by the reference)
#define BB 8192
#define SS 10
#define HH 1024
#define PD_EPS 1e-6f
#define SENTINEL 10.0f
#define MARGIN_EPS 0.5f
#define ALPHA_ROWS 16200   // 2700*6
#define ALPHA_COLS 10

#define MTHREADS 256       // threads per margin block: 1024/4 = 256 float4 lanes
#define ATHREADS 256
#define ABLOCKS  64

// Deterministic partial-sum scratch (no device alloc allowed)
__device__ float g_margin_part[BB];
__device__ float g_alpha_part[ABLOCKS];

// ---------------------------------------------------------------------------
// Margin kernel: one CTA per batch row. Streams sentence row (4 KB) and the
// 10 gloss rows (40 KB) with fully-coalesced float4 loads; each thread keeps
// 10 per-sense partial SSE accumulators -> MLP = 11 LDG.128 per thread.
// ---------------------------------------------------------------------------
__global__ void __launch_bounds__(MTHREADS)
margin_kernel(const float* __restrict__ sentence,
              const float* __restrict__ gloss,
              const int*   __restrict__ mask,
              const int*   __restrict__ sids)
{
    const int b = blockIdx.x;
    const int t = threadIdx.x;

    const float4* __restrict__ sent4 = (const float4*)(sentence + (size_t)b * HH);
    const float4* __restrict__ gl4   = (const float4*)(gloss + (size_t)b * SS * HH);

    const float4 sv = sent4[t];

    float acc[SS];
#pragma unroll
    for (int s = 0; s < SS; s++) {
        const float4 g = gl4[s * (HH / 4) + t];
        float d0 = sv.x - g.x + PD_EPS;
        float d1 = sv.y - g.y + PD_EPS;
        float d2 = sv.z - g.z + PD_EPS;
        float d3 = sv.w - g.w + PD_EPS;
        acc[s] = d0 * d0 + d1 * d1 + d2 * d2 + d3 * d3;
    }

    // Warp reduction for each of the 10 accumulators
#pragma unroll
    for (int s = 0; s < SS; s++) {
        float v = acc[s];
#pragma unroll
        for (int o = 16; o > 0; o >>= 1)
            v += __shfl_down_sync(0xffffffffu, v, o);
        acc[s] = v;
    }

    __shared__ float sm[MTHREADS / 32][SS];
    const int warp = t >> 5;
    const int lane = t & 31;
    if (lane == 0) {
#pragma unroll
        for (int s = 0; s < SS; s++) sm[warp][s] = acc[s];
    }
    __syncthreads();

    if (t == 0) {
        float d[SS];
#pragma unroll
        for (int s = 0; s < SS; s++) {
            float v = 0.0f;
#pragma unroll
            for (int w = 0; w < MTHREADS / 32; w++) v += sm[w][s];
            d[s] = sqrtf(v);
        }

        const int sid = sids[b];
        const float pos = d[sid];

        // masked argmin with first-index tie-break (ascending scan, strict <)
        float best = 1e30f;
        int   bi   = 0;
#pragma unroll
        for (int s = 0; s < SS; s++) {
            const bool valid = (mask[b * SS + s] != 0) && (s != sid);
            const float m = valid ? d[s] : SENTINEL;
            if (m < best) { best = m; bi = s; }
        }
        // neg is the TRUE distance at the argmin index (matches reference even
        // when every sense is invalid and the argmin falls on a sentinel slot)
        const float neg = d[bi];

        const float h = pos - neg + MARGIN_EPS;
        g_margin_part[b] = (h > 0.0f) ? h : 0.0f;
    }
}

// ---------------------------------------------------------------------------
// Alpha kernel: 16200 rows of 10 floats. Tiny (648 KB) -> negligible either way.
// contrib = (rowsum == 0) ? 0 : |rowmax - 1|
// ---------------------------------------------------------------------------
__global__ void __launch_bounds__(ATHREADS)
alpha_kernel(const float* __restrict__ alpha)
{
    const int tid = threadIdx.x;
    float local = 0.0f;

    for (int r = blockIdx.x * ATHREADS + tid; r < ALPHA_ROWS; r += ABLOCKS * ATHREADS) {
        const float* row = alpha + (size_t)r * ALPHA_COLS;
        float rsum = 0.0f;
        float rmax = -1e30f;
#pragma unroll
        for (int c = 0; c < ALPHA_COLS; c++) {
            const float v = row[c];
            rsum += v;
            rmax = fmaxf(rmax, v);
        }
        local += (rsum == 0.0f) ? 0.0f : fabsf(rmax - 1.0f);
    }

    // block reduce
#pragma unroll
    for (int o = 16; o > 0; o >>= 1)
        local += __shfl_down_sync(0xffffffffu, local, o);

    __shared__ float sw[ATHREADS / 32];
    const int warp = tid >> 5;
    const int lane = tid & 31;
    if (lane == 0) sw[warp] = local;
    __syncthreads();
    if (tid == 0) {
        float v = 0.0f;
#pragma unroll
        for (int w = 0; w < ATHREADS / 32; w++) v += sw[w];
        g_alpha_part[blockIdx.x] = v;
    }
}

// ---------------------------------------------------------------------------
// Finalize: deterministic double-precision reduction of partials, writes out.
// ---------------------------------------------------------------------------
__global__ void __launch_bounds__(256)
finalize_kernel(float* __restrict__ out, int out_size)
{
    const int t = threadIdx.x;
    const int lane = t & 31;
    const int warp = t >> 5;
    __shared__ double sm[8];

    // margin sum (fixed iteration order -> deterministic)
    double m = 0.0;
    for (int i = t; i < BB; i += 256) m += (double)g_margin_part[i];
#pragma unroll
    for (int o = 16; o > 0; o >>= 1) m += __shfl_down_sync(0xffffffffu, m, o);
    if (lane == 0) sm[warp] = m;
    __syncthreads();
    double margin = 0.0;
    if (t == 0) {
#pragma unroll
        for (int w = 0; w < 8; w++) margin += sm[w];
    }
    __syncthreads();

    // alpha sum
    double a = 0.0;
    if (t < ABLOCKS) a = (double)g_alpha_part[t];
#pragma unroll
    for (int o = 16; o > 0; o >>= 1) a += __shfl_down_sync(0xffffffffu, a, o);
    if (lane == 0) sm[warp] = a;
    __syncthreads();

    if (t == 0) {
        double alpha_term = 0.0;
#pragma unroll
        for (int w = 0; w < 8; w++) alpha_term += sm[w];

        const double loss = margin * 0.875 + alpha_term * 0.125;
        if (out_size > 0) out[0] = (float)loss;
        if (out_size > 1) out[1] = (float)margin;
        if (out_size > 2) out[2] = (float)alpha_term;
        for (int i = 3; i < out_size; i++) out[i] = 0.0f;
    }
}

// ---------------------------------------------------------------------------
extern "C" void kernel_launch(void* const* d_in, const int* in_sizes, int n_in,
                              void* d_out, int out_size)
{
    // Map inputs defensively by element count (all five counts are distinct):
    //   sentence 8192*1024=8388608, all_gloss 83886080, alpha 162000,
    //   sense_mask 81920, sense_ids 8192
    const float* sentence = nullptr;
    const float* all_gloss = nullptr;
    const float* alpha = nullptr;
    const int*   sense_mask = nullptr;
    const int*   sense_ids = nullptr;

    for (int i = 0; i < n_in; i++) {
        switch (in_sizes[i]) {
            case 8388608:  sentence   = (const float*)d_in[i]; break;
            case 83886080: all_gloss  = (const float*)d_in[i]; break;
            case 162000:   alpha      = (const float*)d_in[i]; break;
            case 81920:    sense_mask = (const int*)d_in[i];   break;
            case 8192:     sense_ids  = (const int*)d_in[i];   break;
            default: break;
        }
    }

    margin_kernel<<<BB, MTHREADS>>>(sentence, all_gloss, sense_mask, sense_ids);
    alpha_kernel<<<ABLOCKS, ATHREADS>>>(alpha);
    finalize_kernel<<<1, 256>>>((float*)d_out, out_size);
}

// round 2
// speedup vs baseline: 1.0692x; 1.0692x over previous
#include <cuda_runtime.h>
#include <math.h>

// Problem constants (fixed by the reference)
#define BB 8192
#define SS 10
#define HH 1024
#define PD_EPS 1e-6f
#define SENTINEL 10.0f
#define MARGIN_EPS 0.5f
#define ALPHA_ROWS 16200   // 2700*6
#define ALPHA_COLS 10

#define MCTAS 512          // margin CTAs: 512*8 warps = 4096 warps, 2 rows each
#define ACTAS 32           // alpha CTAs
#define WPB   8            // warps per block

// Deterministic partial-sum scratch (no device alloc allowed)
__device__ float g_margin_part[BB];
__device__ float g_alpha_part[ACTAS];

// ---------------------------------------------------------------------------
// Fused kernel:
//   CTAs [0, MCTAS)        : margin term, one WARP per batch row (2 rows/warp).
//                            No smem, no __syncthreads — pure streaming +
//                            warp-shuffle reduction. Max load-issue density.
//   CTAs [MCTAS, MCTAS+32) : alpha term (tiny, 648 KB).
// ---------------------------------------------------------------------------
__global__ void __launch_bounds__(256, 4)
fused_kernel(const float* __restrict__ sentence,
             const float* __restrict__ gloss,
             const int*   __restrict__ mask,
             const int*   __restrict__ sids,
             const float* __restrict__ alpha)
{
    if (blockIdx.x < MCTAS) {
        // ---------------- margin: warp-per-row ----------------
        const int lane  = threadIdx.x & 31;
        const int gwarp = blockIdx.x * WPB + (threadIdx.x >> 5);

        for (int b = gwarp; b < BB; b += MCTAS * WPB) {
            // Broadcast target id; lanes 0..9 fetch the 10 mask ints (coalesced)
            const int sid = __ldg(&sids[b]);
            int mv = 0;
            if (lane < SS) mv = __ldg(&mask[b * SS + lane]);
            const unsigned validbits = __ballot_sync(0xffffffffu,
                (lane < SS) && (mv != 0) && (lane != sid));

            const float4* __restrict__ s4 =
                (const float4*)(sentence + (size_t)b * HH);
            const float4* __restrict__ g4 =
                (const float4*)(gloss + (size_t)b * SS * HH);

            float acc[SS];
#pragma unroll
            for (int s = 0; s < SS; s++) acc[s] = 0.0f;

            // 8 chunks; each chunk: 1 sentence LDG.128 + 10 gloss LDG.128,
            // all independent -> high MLP. Partial unroll keeps regs <= 64.
#pragma unroll 2
            for (int c = 0; c < 8; c++) {
                const int idx = c * 32 + lane;
                const float4 sv = s4[idx];
#pragma unroll
                for (int s = 0; s < SS; s++) {
                    const float4 g = g4[s * (HH / 4) + idx];
                    const float d0 = sv.x - g.x + PD_EPS;
                    const float d1 = sv.y - g.y + PD_EPS;
                    const float d2 = sv.z - g.z + PD_EPS;
                    const float d3 = sv.w - g.w + PD_EPS;
                    acc[s] += d0 * d0 + d1 * d1 + d2 * d2 + d3 * d3;
                }
            }

            // Warp reduction: 10 independent shfl trees (interleaved by ptxas)
#pragma unroll
            for (int s = 0; s < SS; s++) {
                float v = acc[s];
#pragma unroll
                for (int o = 16; o > 0; o >>= 1)
                    v += __shfl_down_sync(0xffffffffu, v, o);
                acc[s] = v;
            }

            if (lane == 0) {
                // pos/neg selection folded into the unrolled loop:
                // no dynamic register indexing -> no local-mem spill.
                float pos = 0.0f, negd = 0.0f, best = 1e30f;
#pragma unroll
                for (int s = 0; s < SS; s++) {
                    const float ds = sqrtf(acc[s]);
                    if (s == sid) pos = ds;
                    const float m = ((validbits >> s) & 1u) ? ds : SENTINEL;
                    if (m < best) { best = m; negd = ds; }  // strict < = first-tie
                }
                const float h = pos - negd + MARGIN_EPS;
                g_margin_part[b] = (h > 0.0f) ? h : 0.0f;
            }
        }
    } else {
        // ---------------- alpha term ----------------
        const int aid = blockIdx.x - MCTAS;
        const int tid = threadIdx.x;
        float local = 0.0f;

        for (int r = aid * 256 + tid; r < ALPHA_ROWS; r += ACTAS * 256) {
            const float* row = alpha + (size_t)r * ALPHA_COLS;
            float rsum = 0.0f;
            float rmax = -1e30f;
#pragma unroll
            for (int c = 0; c < ALPHA_COLS; c++) {
                const float v = __ldg(&row[c]);
                rsum += v;
                rmax = fmaxf(rmax, v);
            }
            local += (rsum == 0.0f) ? 0.0f : fabsf(rmax - 1.0f);
        }

#pragma unroll
        for (int o = 16; o > 0; o >>= 1)
            local += __shfl_down_sync(0xffffffffu, local, o);

        __shared__ float sw[8];
        const int warp = tid >> 5;
        const int lane = tid & 31;
        if (lane == 0) sw[warp] = local;
        __syncthreads();
        if (tid == 0) {
            float v = 0.0f;
#pragma unroll
            for (int w = 0; w < 8; w++) v += sw[w];
            g_alpha_part[aid] = v;
        }
    }
}

// ---------------------------------------------------------------------------
// Finalize: deterministic double-precision reduction of partials, writes out.
// ---------------------------------------------------------------------------
__global__ void __launch_bounds__(256)
finalize_kernel(float* __restrict__ out, int out_size)
{
    const int t = threadIdx.x;
    const int lane = t & 31;
    const int warp = t >> 5;
    __shared__ double sm[8];

    // margin sum (fixed iteration order -> deterministic)
    double m = 0.0;
    for (int i = t; i < BB; i += 256) m += (double)g_margin_part[i];
#pragma unroll
    for (int o = 16; o > 0; o >>= 1) m += __shfl_down_sync(0xffffffffu, m, o);
    if (lane == 0) sm[warp] = m;
    __syncthreads();
    double margin = 0.0;
    if (t == 0) {
#pragma unroll
        for (int w = 0; w < 8; w++) margin += sm[w];
    }
    __syncthreads();

    // alpha sum
    double a = 0.0;
    if (t < ACTAS) a = (double)g_alpha_part[t];
#pragma unroll
    for (int o = 16; o > 0; o >>= 1) a += __shfl_down_sync(0xffffffffu, a, o);
    if (lane == 0) sm[warp] = a;
    __syncthreads();

    if (t == 0) {
        double alpha_term = 0.0;
#pragma unroll
        for (int w = 0; w < 8; w++) alpha_term += sm[w];

        const double loss = margin * 0.875 + alpha_term * 0.125;
        if (out_size > 0) out[0] = (float)loss;
        if (out_size > 1) out[1] = (float)margin;
        if (out_size > 2) out[2] = (float)alpha_term;
        for (int i = 3; i < out_size; i++) out[i] = 0.0f;
    }
}

// ---------------------------------------------------------------------------
extern "C" void kernel_launch(void* const* d_in, const int* in_sizes, int n_in,
                              void* d_out, int out_size)
{
    // Map inputs defensively by element count (all five counts are distinct):
    //   sentence 8388608, all_gloss 83886080, alpha 162000,
    //   sense_mask 81920, sense_ids 8192
    const float* sentence = nullptr;
    const float* all_gloss = nullptr;
    const float* alpha = nullptr;
    const int*   sense_mask = nullptr;
    const int*   sense_ids = nullptr;

    for (int i = 0; i < n_in; i++) {
        switch (in_sizes[i]) {
            case 8388608:  sentence   = (const float*)d_in[i]; break;
            case 83886080: all_gloss  = (const float*)d_in[i]; break;
            case 162000:   alpha      = (const float*)d_in[i]; break;
            case 81920:    sense_mask = (const int*)d_in[i];   break;
            case 8192:     sense_ids  = (const int*)d_in[i];   break;
            default: break;
        }
    }

    fused_kernel<<<MCTAS + ACTAS, 256>>>(sentence, all_gloss, sense_mask,
                                         sense_ids, alpha);
    finalize_kernel<<<1, 256>>>((float*)d_out, out_size);
}

// round 3
// speedup vs baseline: 1.1026x; 1.0312x over previous
#include <cuda_runtime.h>
#include <math.h>

// Problem constants (fixed by the reference)
#define BB 8192
#define SS 10
#define HH 1024
#define PD_EPS 1e-6f
#define SENTINEL 10.0f
#define MARGIN_EPS 0.5f
#define ALPHA_ROWS 16200   // 2700*6
#define ALPHA_COLS 10

#define MCTAS 512          // margin CTAs: 512*8 warps = 4096 warps, 2 rows each
#define ACTAS 32           // alpha CTAs
#define WPB   8            // warps per block
#define TOTAL_CTAS (MCTAS + ACTAS)

// Deterministic partial-sum scratch (no device alloc allowed)
__device__ float    g_margin_part[MCTAS];   // one per margin CTA
__device__ float    g_alpha_part[ACTAS];    // one per alpha CTA
__device__ unsigned g_ticket;               // zero-initialized; reset by last CTA

// ---------------------------------------------------------------------------
// Single fused kernel:
//   CTAs [0, MCTAS)   : margin term, one WARP per batch row (2 rows/warp).
//   CTAs [MCTAS, ..)  : alpha term (tiny, 648 KB).
//   Last CTA to finish: deterministic final combine + output write, then
//   resets the ticket so replays (CUDA graph) behave identically.
// ---------------------------------------------------------------------------
__global__ void __launch_bounds__(256, 4)
fused_kernel(const float* __restrict__ sentence,
             const float* __restrict__ gloss,
             const int*   __restrict__ mask,
             const int*   __restrict__ sids,
             const float* __restrict__ alpha,
             float* __restrict__ out, int out_size)
{
    const int tid  = threadIdx.x;
    const int lane = tid & 31;
    const int warp = tid >> 5;
    __shared__ float s_part[WPB];

    if (blockIdx.x < MCTAS) {
        // ---------------- margin: warp-per-row ----------------
        const int gwarp = blockIdx.x * WPB + warp;
        float hinge_sum = 0.0f;   // this warp's rows (lane 0 accumulates)

        for (int b = gwarp; b < BB; b += MCTAS * WPB) {
            const int sid = __ldg(&sids[b]);
            int mv = 0;
            if (lane < SS) mv = __ldg(&mask[b * SS + lane]);
            const unsigned validbits = __ballot_sync(0xffffffffu,
                (lane < SS) && (mv != 0) && (lane != sid));

            const float4* __restrict__ s4 =
                (const float4*)(sentence + (size_t)b * HH);
            const float4* __restrict__ g4 =
                (const float4*)(gloss + (size_t)b * SS * HH);

            float acc[SS];
#pragma unroll
            for (int s = 0; s < SS; s++) acc[s] = 0.0f;

            // 8 chunks; each chunk: 1 sentence LDG.128 + 10 gloss LDG.128,
            // all independent -> high MLP. Partial unroll keeps regs bounded.
#pragma unroll 2
            for (int c = 0; c < 8; c++) {
                const int idx = c * 32 + lane;
                const float4 sv = s4[idx];
#pragma unroll
                for (int s = 0; s < SS; s++) {
                    const float4 g = g4[s * (HH / 4) + idx];
                    const float d0 = sv.x - g.x + PD_EPS;
                    const float d1 = sv.y - g.y + PD_EPS;
                    const float d2 = sv.z - g.z + PD_EPS;
                    const float d3 = sv.w - g.w + PD_EPS;
                    acc[s] += d0 * d0 + d1 * d1 + d2 * d2 + d3 * d3;
                }
            }

            // Warp reduction: 10 independent shfl trees
#pragma unroll
            for (int s = 0; s < SS; s++) {
                float v = acc[s];
#pragma unroll
                for (int o = 16; o > 0; o >>= 1)
                    v += __shfl_down_sync(0xffffffffu, v, o);
                acc[s] = v;
            }

            if (lane == 0) {
                float pos = 0.0f, negd = 0.0f, best = 1e30f;
#pragma unroll
                for (int s = 0; s < SS; s++) {
                    const float ds = sqrtf(acc[s]);
                    if (s == sid) pos = ds;
                    const float m = ((validbits >> s) & 1u) ? ds : SENTINEL;
                    if (m < best) { best = m; negd = ds; }  // strict < = first-tie
                }
                const float h = pos - negd + MARGIN_EPS;
                hinge_sum += (h > 0.0f) ? h : 0.0f;
            }
        }

        // CTA-level combine (deterministic order)
        if (lane == 0) s_part[warp] = hinge_sum;
        __syncthreads();
        if (tid == 0) {
            float v = 0.0f;
#pragma unroll
            for (int w = 0; w < WPB; w++) v += s_part[w];
            g_margin_part[blockIdx.x] = v;
        }
    } else {
        // ---------------- alpha term ----------------
        const int aid = blockIdx.x - MCTAS;
        float local = 0.0f;

        for (int r = aid * 256 + tid; r < ALPHA_ROWS; r += ACTAS * 256) {
            const float* row = alpha + (size_t)r * ALPHA_COLS;
            float rsum = 0.0f;
            float rmax = -1e30f;
#pragma unroll
            for (int c = 0; c < ALPHA_COLS; c++) {
                const float v = __ldg(&row[c]);
                rsum += v;
                rmax = fmaxf(rmax, v);
            }
            local += (rsum == 0.0f) ? 0.0f : fabsf(rmax - 1.0f);
        }

#pragma unroll
        for (int o = 16; o > 0; o >>= 1)
            local += __shfl_down_sync(0xffffffffu, local, o);

        if (lane == 0) s_part[warp] = local;
        __syncthreads();
        if (tid == 0) {
            float v = 0.0f;
#pragma unroll
            for (int w = 0; w < WPB; w++) v += s_part[w];
            g_alpha_part[aid] = v;
        }
    }

    // ---------------- last-CTA finalize ----------------
    __shared__ unsigned s_is_last;
    __threadfence();                 // make partial visible before ticket bump
    __syncthreads();                 // all threads of CTA done
    if (tid == 0)
        s_is_last = (atomicAdd(&g_ticket, 1u) == TOTAL_CTAS - 1u) ? 1u : 0u;
    __syncthreads();

    if (s_is_last) {
        __shared__ double sm[8];

        // margin: 512 partials, fixed order -> deterministic
        double m = 0.0;
        for (int i = tid; i < MCTAS; i += 256) m += (double)g_margin_part[i];
#pragma unroll
        for (int o = 16; o > 0; o >>= 1) m += __shfl_down_sync(0xffffffffu, m, o);
        if (lane == 0) sm[warp] = m;
        __syncthreads();
        double margin = 0.0;
        if (tid == 0) {
#pragma unroll
            for (int w = 0; w < 8; w++) margin += sm[w];
        }
        __syncthreads();

        // alpha: 32 partials
        double a = (tid < ACTAS) ? (double)g_alpha_part[tid] : 0.0;
#pragma unroll
        for (int o = 16; o > 0; o >>= 1) a += __shfl_down_sync(0xffffffffu, a, o);
        if (lane == 0) sm[warp] = a;
        __syncthreads();

        if (tid == 0) {
            double alpha_term = 0.0;
#pragma unroll
            for (int w = 0; w < 8; w++) alpha_term += sm[w];

            const double loss = margin * 0.875 + alpha_term * 0.125;
            if (out_size > 0) out[0] = (float)loss;
            if (out_size > 1) out[1] = (float)margin;
            if (out_size > 2) out[2] = (float)alpha_term;
            for (int i = 3; i < out_size; i++) out[i] = 0.0f;

            g_ticket = 0;            // reset for next graph replay
        }
    }
}

// ---------------------------------------------------------------------------
extern "C" void kernel_launch(void* const* d_in, const int* in_sizes, int n_in,
                              void* d_out, int out_size)
{
    // Map inputs defensively by element count (all five counts are distinct):
    //   sentence 8388608, all_gloss 83886080, alpha 162000,
    //   sense_mask 81920, sense_ids 8192
    const float* sentence = nullptr;
    const float* all_gloss = nullptr;
    const float* alpha = nullptr;
    const int*   sense_mask = nullptr;
    const int*   sense_ids = nullptr;

    for (int i = 0; i < n_in; i++) {
        switch (in_sizes[i]) {
            case 8388608:  sentence   = (const float*)d_in[i]; break;
            case 83886080: all_gloss  = (const float*)d_in[i]; break;
            case 162000:   alpha      = (const float*)d_in[i]; break;
            case 81920:    sense_mask = (const int*)d_in[i];   break;
            case 8192:     sense_ids  = (const int*)d_in[i];   break;
            default: break;
        }
    }

    fused_kernel<<<TOTAL_CTAS, 256>>>(sentence, all_gloss, sense_mask,
                                      sense_ids, alpha,
                                      (float*)d_out, out_size);
}